// round 3
// baseline (speedup 1.0000x reference)
#include <cuda_runtime.h>
#include <math.h>

#define NB    2
#define NPTS  16384
#define MPTS  4096
#define CIN   64
#define COUT  128
#define EPSF  1e-10f

#define TM      128       // m-columns per CTA
#define TN      256       // n-rows per chunk
#define KSUB    32        // k sub-chunk staged through smem
#define NSPLIT  16        // n-partitions (grid.y)
#define NPART   (NPTS/NSPLIT)   // 1024 n per CTA
#define SF_STRIDE 258     // padded row stride of the f subtile (floats)

#define XYZ_OFF  0
#define FEAT_OFF (NB*MPTS*3)                 // 24576
#define IDX_OFF  (FEAT_OFF + NB*COUT*MPTS)   // 1073152

// ---------------- device scratch (no allocations allowed) ----------------
__device__ float               g_f[(size_t)NB*NPTS*COUT];   // 16 MB: relu(f W1 + b1)
__device__ unsigned long long  g_best[NB*MPTS];             // packed (key<<32)|(~n)
__device__ int                 g_idx[NB*MPTS];

// ---------------- packed f32x2 helpers (sm_103a FFMA2) ----------------
__device__ __forceinline__ unsigned long long ffma2(unsigned long long a,
                                                    unsigned long long b,
                                                    unsigned long long c) {
    unsigned long long d;
    asm("fma.rn.f32x2 %0, %1, %2, %3;" : "=l"(d) : "l"(a), "l"(b), "l"(c));
    return d;
}
__device__ __forceinline__ unsigned long long dup2(float x) {
    unsigned long long d; unsigned int r = __float_as_uint(x);
    asm("mov.b64 %0, {%1, %2};" : "=l"(d) : "r"(r), "r"(r));
    return d;
}
__device__ __forceinline__ void unpk(unsigned long long v, float& lo, float& hi) {
    unsigned int a, b;
    asm("mov.b64 {%0, %1}, %2;" : "=r"(a), "=r"(b) : "l"(v));
    lo = __uint_as_float(a); hi = __uint_as_float(b);
}

// ---------------- gumbel + argmax key ----------------
// Accurate logf for BOTH logs: __logf's 2^-21 absolute error is catastrophic
// for the inner log when u is near 1 (t = -log(u) ~ 1e-7, and those are the
// winning gumbels); outer precision also matters for large |g|.
__device__ __forceinline__ float gumbel_g(float uu) {
    float v = uu + EPSF;
    float t = -logf(v);
    return -logf(t + EPSF);
}
// Order-preserving float->uint encode; low word = ~n so ties pick lowest n.
__device__ __forceinline__ unsigned long long mkkey(float x, int n) {
    unsigned int ux = __float_as_uint(x);
    unsigned int ex = (ux & 0x80000000u) ? ~ux : (ux | 0x80000000u);
    return ((unsigned long long)ex << 32) | (unsigned int)(0xFFFFFFFFu - (unsigned)n);
}

// ---------------- kernel 0: init argmax scratch ----------------
__global__ void k_init() {
    int i = blockIdx.x * blockDim.x + threadIdx.x;
    if (i < NB * MPTS) g_best[i] = 0ULL;   // all real keys are > 0
}

// ---------------- kernel A: f = relu(feats^T W1 + b1) ----------------
// feats: (b, Cin, N) [n contiguous], W1: (Cin, Cout), out g_f[b][n][d].
__global__ __launch_bounds__(256) void k_feat(const float* __restrict__ feats,
                                              const float* __restrict__ W1,
                                              const float* __restrict__ b1) {
    extern __shared__ float sm[];
    float* sX = sm;              // [64][132]
    float* sW = sm + 64 * 132;   // [64][128]
    const int b  = blockIdx.y;
    const int n0 = blockIdx.x * 128;
    const int t  = threadIdx.x;

#pragma unroll
    for (int i = 0; i < 8; i++) {                 // feats tile 64c x 128n
        int lin = t + 256 * i;
        int c = lin >> 5, q = lin & 31;
        float4 v = *(const float4*)(feats + ((size_t)(b * CIN + c)) * NPTS + n0 + 4 * q);
        *(float4*)(sX + c * 132 + 4 * q) = v;
    }
#pragma unroll
    for (int i = 0; i < 8; i++) {                 // W1 64x128
        int lin = t + 256 * i;
        int c = lin >> 5, q = lin & 31;
        *(float4*)(sW + c * 128 + 4 * q) = *(const float4*)(W1 + c * 128 + 4 * q);
    }
    __syncthreads();

    const int db = (t & 15) * 8;    // 8 d-cols
    const int nb = (t >> 4) * 8;    // 8 n-rows

    float acc[8][8];
#pragma unroll
    for (int i = 0; i < 8; i++)
#pragma unroll
        for (int j = 0; j < 8; j++) acc[i][j] = 0.0f;

    for (int c = 0; c < CIN; c++) {
        float x[8], w[8];
#pragma unroll
        for (int i = 0; i < 8; i++) x[i] = sX[c * 132 + nb + i];
#pragma unroll
        for (int j = 0; j < 8; j++) w[j] = sW[c * 128 + db + j];
#pragma unroll
        for (int i = 0; i < 8; i++)
#pragma unroll
            for (int j = 0; j < 8; j++) acc[i][j] = fmaf(x[i], w[j], acc[i][j]);
    }

    float bias[8];
#pragma unroll
    for (int j = 0; j < 8; j++) bias[j] = b1[db + j];

#pragma unroll
    for (int i = 0; i < 8; i++) {
        float o[8];
#pragma unroll
        for (int j = 0; j < 8; j++) o[j] = fmaxf(acc[i][j] + bias[j], 0.0f);
        float* dst = g_f + ((size_t)(b) * NPTS + n0 + nb + i) * COUT + db;
        *(float4*)(dst)     = make_float4(o[0], o[1], o[2], o[3]);
        *(float4*)(dst + 4) = make_float4(o[4], o[5], o[6], o[7]);
    }
}

// ---------------- kernel B: fused w-GEMM + gumbel + argmax ----------------
// grid (32 m-tiles, 16 n-partitions, 2 batches), 256 threads.
// Thread tile: 16 n (8 f32x2 pairs) x 8 m. CTA tile per chunk: 256n x 128m.
__global__ __launch_bounds__(256, 1) void k_main(const float* __restrict__ W2,
                                                 const float* __restrict__ u) {
    extern __shared__ float sm[];
    float* sW2 = sm;                          // [128][128]  64 KB, resident
    float* sF  = sm + 128 * 128;              // [32][258]   ~33 KB, staged
    unsigned long long* sBest = (unsigned long long*)(sF + KSUB * SF_STRIDE); // [128]

    const int mt = blockIdx.x, np = blockIdx.y, b = blockIdx.z;
    const int m0 = mt * TM;
    const int t  = threadIdx.x;
    const int m_base = (t & 15) * 8;    // lanes 0-15 of a warp: contiguous m
    const int n_base = (t >> 4) * 16;   // lanes 0-15 share n (smem broadcast)

    if (t < TM) sBest[t] = 0ULL;

#pragma unroll
    for (int i = 0; i < 16; i++) {            // W2 tile [k][m], once per CTA
        int lin = t + 256 * i;
        int k = lin >> 5, q = lin & 31;
        *(float4*)(sW2 + k * 128 + 4 * q) =
            *(const float4*)(W2 + (size_t)k * MPTS + m0 + 4 * q);
    }
    __syncthreads();

    unsigned long long best[8];
#pragma unroll
    for (int j = 0; j < 8; j++) best[j] = 0ULL;

    const float* fbase = g_f + (size_t)b * NPTS * COUT;
    const float* ubase = u   + (size_t)b * NPTS * MPTS;

    for (int ch = 0; ch < NPART / TN; ch++) {
        const int n0 = np * NPART + ch * TN;

        unsigned long long acc[8][8];
#pragma unroll
        for (int p = 0; p < 8; p++)
#pragma unroll
            for (int j = 0; j < 8; j++) acc[p][j] = 0ULL;

        for (int sub = 0; sub < COUT / KSUB; sub++) {
            const int kb = sub * KSUB;
            __syncthreads();
            // stage f subtile transposed: sF[k][n]
#pragma unroll
            for (int i = 0; i < 8; i++) {
                int lin = t + 256 * i;
                int n = lin >> 3, q = lin & 7;
                float4 v = *(const float4*)(fbase + (size_t)(n0 + n) * COUT + kb + 4 * q);
                sF[(4 * q + 0) * SF_STRIDE + n] = v.x;
                sF[(4 * q + 1) * SF_STRIDE + n] = v.y;
                sF[(4 * q + 2) * SF_STRIDE + n] = v.z;
                sF[(4 * q + 3) * SF_STRIDE + n] = v.w;
            }
            __syncthreads();

#pragma unroll 4
            for (int kk = 0; kk < KSUB; kk++) {
                unsigned long long fp[8];
#pragma unroll
                for (int p = 0; p < 8; p++)     // LDS.64 pairs, lane-broadcast
                    fp[p] = *(const unsigned long long*)(sF + kk * SF_STRIDE + n_base + 2 * p);
                const float* wrow = sW2 + (kb + kk) * 128 + m_base;
                float4 wa = *(const float4*)(wrow);
                float4 wb = *(const float4*)(wrow + 4);
                float wv[8] = {wa.x, wa.y, wa.z, wa.w, wb.x, wb.y, wb.z, wb.w};
#pragma unroll
                for (int j = 0; j < 8; j++) {
                    unsigned long long wd = dup2(wv[j]);
#pragma unroll
                    for (int p = 0; p < 8; p++)
                        acc[p][j] = ffma2(fp[p], wd, acc[p][j]);
                }
            }
        }

        // epilogue: add gumbel noise, fold into running argmax keys
#pragma unroll
        for (int p = 0; p < 8; p++) {
            const int nlo = n0 + n_base + 2 * p;
            const float* up0 = ubase + (size_t)nlo * MPTS + m0 + m_base;
            const float* up1 = up0 + MPTS;
            float4 a0 = ((const float4*)up0)[0], a1 = ((const float4*)up0)[1];
            float4 b0 = ((const float4*)up1)[0], b1v = ((const float4*)up1)[1];
            float ul[8] = {a0.x, a0.y, a0.z, a0.w, a1.x, a1.y, a1.z, a1.w};
            float uh[8] = {b0.x, b0.y, b0.z, b0.w, b1v.x, b1v.y, b1v.z, b1v.w};
#pragma unroll
            for (int j = 0; j < 8; j++) {
                float lo, hi;
                unpk(acc[p][j], lo, hi);
                float s0 = lo + gumbel_g(ul[j]);
                float s1 = hi + gumbel_g(uh[j]);
                unsigned long long k0 = mkkey(s0, nlo);
                unsigned long long k1 = mkkey(s1, nlo + 1);
                if (k0 > best[j]) best[j] = k0;
                if (k1 > best[j]) best[j] = k1;
            }
        }
    }

    __syncthreads();
#pragma unroll
    for (int j = 0; j < 8; j++)
        atomicMax(&sBest[m_base + j], best[j]);
    __syncthreads();
    if (t < TM)
        atomicMax(&g_best[(size_t)b * MPTS + m0 + t], sBest[t]);
}

// ---------------- kernel C: decode idx, write xyz + indices ----------------
__global__ void k_pick(const float* __restrict__ xyzs, float* __restrict__ out) {
    int i = blockIdx.x * blockDim.x + threadIdx.x;
    if (i >= NB * MPTS) return;
    int b = i / MPTS;
    unsigned long long key = g_best[i];
    int n = (int)(0xFFFFFFFFu - (unsigned int)(key & 0xFFFFFFFFull));
    g_idx[i] = n;
    const float* x = xyzs + ((size_t)b * NPTS + n) * 3;
    out[XYZ_OFF + 3 * i + 0] = x[0];
    out[XYZ_OFF + 3 * i + 1] = x[1];
    out[XYZ_OFF + 3 * i + 2] = x[2];
    out[IDX_OFF + i] = (float)n;
}

// ---------------- kernel D: gather features, transposed to (b, Cout, M) ----
__global__ void k_gather(float* __restrict__ out) {
    int j = blockIdx.x * blockDim.x + threadIdx.x;
    if (j >= NB * COUT * MPTS) return;
    int b = j / (COUT * MPTS);
    int d = (j / MPTS) % COUT;
    int m = j % MPTS;
    int n = g_idx[b * MPTS + m];
    out[FEAT_OFF + j] = g_f[((size_t)b * NPTS + n) * COUT + d];
}

// ---------------- launch ----------------
extern "C" void kernel_launch(void* const* d_in, const int* in_sizes, int n_in,
                              void* d_out, int out_size) {
    const float* xyzs  = (const float*)d_in[0];
    const float* feats = (const float*)d_in[1];
    const float* u     = (const float*)d_in[2];
    const float* W1    = (const float*)d_in[3];
    const float* b1    = (const float*)d_in[4];
    const float* W2    = (const float*)d_in[5];
    // d_in[6] = b2: constant per m-column -> cannot change the argmax; unused.
    float* out = (float*)d_out;

    const int smemA = (64 * 132 + 64 * 128) * 4;                        // 66560
    const int smemB = (128 * 128 + KSUB * SF_STRIDE) * 4 + TM * 8;      // 99584
    cudaFuncSetAttribute(k_feat, cudaFuncAttributeMaxDynamicSharedMemorySize, smemA);
    cudaFuncSetAttribute(k_main, cudaFuncAttributeMaxDynamicSharedMemorySize, smemB);

    k_init<<<(NB * MPTS + 255) / 256, 256>>>();
    k_feat<<<dim3(NPTS / 128, NB), 256, smemA>>>(feats, W1, b1);
    k_main<<<dim3(MPTS / TM, NSPLIT, NB), 256, smemB>>>(W2, u);
    k_pick<<<(NB * MPTS + 255) / 256, 256>>>(xyzs, out);
    k_gather<<<(NB * COUT * MPTS + 255) / 256, 256>>>(out);
}

// round 8
// speedup vs baseline: 1.1284x; 1.1284x over previous
#include <cuda_runtime.h>
#include <cuda_bf16.h>
#include <cstdint>
#include <math.h>

#define NB    2
#define NPTS  16384
#define MPTS  4096
#define CIN   64
#define COUT  128
#define EPSF  1e-10f

#define NSPLIT   4
#define NPART    (NPTS/NSPLIT)      // 4096
#define NCHUNKS  (NPART/128)        // 32
#define NTILES   (NPTS/128)         // 128 per batch
#define MTILES   (MPTS/128)         // 32
#define NSTAGES  (NCHUNKS*3)        // 96

#define XYZ_OFF  0
#define FEAT_OFF (NB*MPTS*3)
#define IDX_OFF  (FEAT_OFF + NB*COUT*MPTS)

// tile block: [128 rows][64 bf16 cols] SW128 image = 16384 B; split (K=128) = 2 blocks
#define TILE_BYTES   16384
#define SPLIT_BYTES  32768

// ---------------- device scratch ----------------
__device__ float               g_f[(size_t)NB*NPTS*COUT];
__device__ __align__(1024) unsigned char g_fsplit[(size_t)NB*NTILES*3*SPLIT_BYTES];  // 25.2 MB
__device__ __align__(1024) unsigned char g_w2split[(size_t)MTILES*3*SPLIT_BYTES];    // 3 MB
__device__ unsigned long long  g_best[NB*MPTS];
__device__ int                 g_idx[NB*MPTS];

// ---------------- helpers ----------------
__device__ __forceinline__ uint32_t smem_u32(const void* p) {
    uint32_t a;
    asm("{ .reg .u64 t; cvta.to.shared.u64 t, %1; cvt.u32.u64 %0, t; }" : "=r"(a) : "l"(p));
    return a;
}
#define SW128(x) ((x) ^ (((x) >> 3) & 0x70))

__device__ __forceinline__ uint32_t enc_f(float x) {
    uint32_t u = __float_as_uint(x);
    return u ^ (((uint32_t)((int32_t)u >> 31)) | 0x80000000u);
}
struct Split3 { __nv_bfloat16 a, b, c; };
__device__ __forceinline__ Split3 split3(float v) {
    Split3 s;
    s.a = __float2bfloat16_rn(v);
    float r = v - __bfloat162float(s.a);
    s.b = __float2bfloat16_rn(r);
    float r2 = r - __bfloat162float(s.b);
    s.c = __float2bfloat16_rn(r2);
    return s;
}
__device__ __forceinline__ uint32_t pk2(__nv_bfloat16 lo, __nv_bfloat16 hi) {
    __nv_bfloat162 t(lo, hi);
    return *(uint32_t*)&t;
}

__device__ __forceinline__ void ldsm_x4(uint32_t* r, uint32_t addr) {
    asm volatile("ldmatrix.sync.aligned.m8n8.x4.shared.b16 {%0,%1,%2,%3}, [%4];"
        : "=r"(r[0]), "=r"(r[1]), "=r"(r[2]), "=r"(r[3]) : "r"(addr));
}
// B operand: smem tile is n-major (k contiguous) -> NON-trans ldmatrix gives
// exactly the mma.row.col B fragment (k=(lane%4)*2+e, n=lane/4). (.trans here
// was the Round-7 bug: it delivered the k/n-swapped fragment.)
__device__ __forceinline__ void ldsm_x2(uint32_t* r, uint32_t addr) {
    asm volatile("ldmatrix.sync.aligned.m8n8.x2.shared.b16 {%0,%1}, [%2];"
        : "=r"(r[0]), "=r"(r[1]) : "r"(addr));
}
__device__ __forceinline__ void mma16816(float* c, const uint32_t* a, const uint32_t* b) {
    asm volatile("mma.sync.aligned.m16n8k16.row.col.f32.bf16.bf16.f32 "
        "{%0,%1,%2,%3}, {%4,%5,%6,%7}, {%8,%9}, {%0,%1,%2,%3};"
        : "+f"(c[0]), "+f"(c[1]), "+f"(c[2]), "+f"(c[3])
        : "r"(a[0]), "r"(a[1]), "r"(a[2]), "r"(a[3]), "r"(b[0]), "r"(b[1]));
}
__device__ __forceinline__ void cp16(uint32_t dst, const void* src) {
    asm volatile("cp.async.cg.shared.global [%0], [%1], 16;" :: "r"(dst), "l"(src) : "memory");
}
#define CP_COMMIT() asm volatile("cp.async.commit_group;" ::: "memory")
#define CP_WAIT0()  asm volatile("cp.async.wait_group 0;" ::: "memory")

// ---------------- kernel 0: init ----------------
__global__ void k_init() {
    int i = blockIdx.x * blockDim.x + threadIdx.x;
    if (i < NB * MPTS) g_best[i] = 0ULL;
}

// ---------------- kernel W: split W2^T into bf16 SW128 tiles ----------------
// tile layout per mt: [split][khalf][128 m-rows x 64 k x bf16, SW128]
__global__ void k_w2split(const float* __restrict__ W2) {
    int mt = blockIdx.x, ml = threadIdx.x;
    for (int k = 0; k < COUT; k++) {
        float v = W2[(size_t)k * MPTS + mt * 128 + ml];
        Split3 s = split3(v);
        size_t base = (size_t)mt * 3 * SPLIT_BYTES + (k >> 6) * TILE_BYTES;
        uint32_t off = SW128((uint32_t)(ml * 128 + (k & 63) * 2));
        *(__nv_bfloat16*)(g_w2split + base + off) = s.a;
        *(__nv_bfloat16*)(g_w2split + base + SPLIT_BYTES + off) = s.b;
        *(__nv_bfloat16*)(g_w2split + base + 2 * SPLIT_BYTES + off) = s.c;
    }
}

// ---------------- kernel A: f = relu(feats^T W1 + b1), fp32 + bf16 splits ----
__global__ __launch_bounds__(256) void k_feat(const float* __restrict__ feats,
                                              const float* __restrict__ W1,
                                              const float* __restrict__ b1) {
    extern __shared__ float sm[];
    float* sX = sm;              // [64][132]
    float* sW = sm + 64 * 132;   // [64][128]
    const int b  = blockIdx.y;
    const int ntile = blockIdx.x;
    const int n0 = ntile * 128;
    const int t  = threadIdx.x;

#pragma unroll
    for (int i = 0; i < 8; i++) {
        int lin = t + 256 * i;
        int c = lin >> 5, q = lin & 31;
        float4 v = *(const float4*)(feats + ((size_t)(b * CIN + c)) * NPTS + n0 + 4 * q);
        *(float4*)(sX + c * 132 + 4 * q) = v;
    }
#pragma unroll
    for (int i = 0; i < 8; i++) {
        int lin = t + 256 * i;
        int c = lin >> 5, q = lin & 31;
        *(float4*)(sW + c * 128 + 4 * q) = *(const float4*)(W1 + c * 128 + 4 * q);
    }
    __syncthreads();

    const int db = (t & 15) * 8;
    const int nb = (t >> 4) * 8;

    float acc[8][8];
#pragma unroll
    for (int i = 0; i < 8; i++)
#pragma unroll
        for (int j = 0; j < 8; j++) acc[i][j] = 0.0f;

    for (int c = 0; c < CIN; c++) {
        float x[8], w[8];
#pragma unroll
        for (int i = 0; i < 8; i++) x[i] = sX[c * 132 + nb + i];
#pragma unroll
        for (int j = 0; j < 8; j++) w[j] = sW[c * 128 + db + j];
#pragma unroll
        for (int i = 0; i < 8; i++)
#pragma unroll
            for (int j = 0; j < 8; j++) acc[i][j] = fmaf(x[i], w[j], acc[i][j]);
    }

    float bias[8];
#pragma unroll
    for (int j = 0; j < 8; j++) bias[j] = b1[db + j];

    const int h = db >> 6;
    unsigned char* tile0 = g_fsplit + (((size_t)(b * NTILES + ntile) * 3 + 0) * 2 + h) * TILE_BYTES;

#pragma unroll
    for (int i = 0; i < 8; i++) {
        float o[8];
#pragma unroll
        for (int j = 0; j < 8; j++) o[j] = fmaxf(acc[i][j] + bias[j], 0.0f);
        float* dst = g_f + ((size_t)(b) * NPTS + n0 + nb + i) * COUT + db;
        *(float4*)(dst)     = make_float4(o[0], o[1], o[2], o[3]);
        *(float4*)(dst + 4) = make_float4(o[4], o[5], o[6], o[7]);

        uint4 p0, p1, p2;
        Split3 s0 = split3(o[0]), s1 = split3(o[1]), s2 = split3(o[2]), s3 = split3(o[3]);
        Split3 s4 = split3(o[4]), s5 = split3(o[5]), s6 = split3(o[6]), s7 = split3(o[7]);
        p0.x = pk2(s0.a, s1.a); p0.y = pk2(s2.a, s3.a); p0.z = pk2(s4.a, s5.a); p0.w = pk2(s6.a, s7.a);
        p1.x = pk2(s0.b, s1.b); p1.y = pk2(s2.b, s3.b); p1.z = pk2(s4.b, s5.b); p1.w = pk2(s6.b, s7.b);
        p2.x = pk2(s0.c, s1.c); p2.y = pk2(s2.c, s3.c); p2.z = pk2(s4.c, s5.c); p2.w = pk2(s6.c, s7.c);
        uint32_t off = SW128((uint32_t)((nb + i) * 128 + (db & 63) * 2));
        *(uint4*)(tile0 + off) = p0;
        *(uint4*)(tile0 + 2 * TILE_BYTES + off) = p1;
        *(uint4*)(tile0 + 4 * TILE_BYTES + off) = p2;
    }
}

// ---------------- kernel B: HMMA w-GEMM (6-product bf16 split) + gumbel + argmax
// grid (32 mt, 4 np, 2 b), 256 threads = 8 warps; warp tile 64m x 32n.
#define SM_W2   0                       // 3 x 32768 = 98304
#define SM_F    98304                   // 2 x 32768 = 65536
#define SM_BEST 163840                  // 128 x 8    = 1024
#define SM_TOT  164864

__global__ __launch_bounds__(256, 1) void k_main(const float* __restrict__ u) {
    extern __shared__ unsigned char smc[];
    const uint32_t smem_base = smem_u32(smc);
    const int t = threadIdx.x, lane = t & 31, wid = t >> 5;
    const int wm = wid >> 2;           // m half (64)
    const int wn = wid & 3;            // n quarter (32)
    const int mt = blockIdx.x, np = blockIdx.y, b = blockIdx.z;
    unsigned long long* sBest = (unsigned long long*)(smc + SM_BEST);

    if (t < 128) sBest[t] = 0ULL;

    // W2 splits resident (linear copy of SW128 images)
    {
        const uint4* src = (const uint4*)(g_w2split + (size_t)mt * 3 * SPLIT_BYTES);
        uint4* dst = (uint4*)(smc + SM_W2);
        for (int i = t; i < 3 * SPLIT_BYTES / 16; i += 256) dst[i] = src[i];
    }
    __syncthreads();

    const unsigned char* fbase = g_fsplit + (size_t)(b * NTILES + np * NCHUNKS) * 3 * SPLIT_BYTES;

    // prefetch stage 0
    {
        uint32_t d = smem_base + SM_F + (t * 16);
        const unsigned char* s = fbase + t * 16;
#pragma unroll
        for (int i = 0; i < 8; i++) cp16(d + i * 4096, s + i * 4096);
        CP_COMMIT();
    }

    // ldmatrix address components (within a 16KB half image)
    const uint32_t a_row = (uint32_t)(wm * 64 + (lane & 15)) * 128 + (lane >> 4) * 16;
    const int lb = lane & 15;
    const uint32_t b_row = (uint32_t)(wn * 32 + (lb & 7)) * 128 + ((lb >> 3) & 1) * 16;

    float acc[4][4][4];
#pragma unroll
    for (int mi = 0; mi < 4; mi++)
#pragma unroll
        for (int ni = 0; ni < 4; ni++)
#pragma unroll
            for (int q = 0; q < 4; q++) acc[mi][ni][q] = 0.0f;

    unsigned long long bestk[8];
#pragma unroll
    for (int q = 0; q < 8; q++) bestk[q] = 0ULL;

    const float* ubase = u + (size_t)b * NPTS * MPTS + (size_t)mt * 128
                           + wm * 64 + (lane >> 2);

    for (int st = 0; st < NSTAGES; st++) {
        const int c = st / 3, s = st - 3 * c;
        const int buf = st & 1;

        CP_WAIT0();
        __syncthreads();
        // prefetch next stage into other buffer
        if (st + 1 < NSTAGES) {
            uint32_t d = smem_base + SM_F + (buf ^ 1) * SPLIT_BYTES + t * 16;
            const unsigned char* sp = fbase + (size_t)(st + 1) * SPLIT_BYTES + t * 16;
#pragma unroll
            for (int i = 0; i < 8; i++) cp16(d + i * 4096, sp + i * 4096);
        }
        CP_COMMIT();

        const int nprod = (s == 0) ? 3 : (s == 1 ? 2 : 1);
        const uint32_t fb0 = smem_base + SM_F + buf * SPLIT_BYTES;

#pragma unroll
        for (int kh = 0; kh < 2; kh++) {
            const uint32_t fhb = fb0 + kh * TILE_BYTES;
            const uint32_t whb = smem_base + SM_W2 + kh * TILE_BYTES;
#pragma unroll
            for (int ks = 0; ks < 4; ks++) {
                uint32_t bf[4][2];
#pragma unroll
                for (int ni = 0; ni < 4; ni++)
                    ldsm_x2(bf[ni], fhb + SW128(b_row + (uint32_t)ni * 8 * 128 + ks * 32));
                for (int sw = 0; sw < nprod; sw++) {
                    const uint32_t wsb = whb + sw * SPLIT_BYTES;
#pragma unroll
                    for (int mi = 0; mi < 4; mi++) {
                        uint32_t af[4];
                        ldsm_x4(af, wsb + SW128(a_row + (uint32_t)mi * 16 * 128 + ks * 32));
#pragma unroll
                        for (int ni = 0; ni < 4; ni++)
                            mma16816(acc[mi][ni], af, bf[ni]);
                    }
                }
            }
        }

        if (s == 2) {
            // epilogue for chunk c: gumbel + argmax, then reset acc
            const int n0c = np * NPART + c * 128;
#pragma unroll
            for (int mi = 0; mi < 4; mi++)
#pragma unroll
                for (int hh = 0; hh < 2; hh++) {
                    const int slot = mi * 2 + hh;
                    uint32_t bk = (uint32_t)(bestk[slot] >> 32);
                    int bn = (int)(0xFFFFFFFFu - (uint32_t)bestk[slot]);
#pragma unroll
                    for (int ni = 0; ni < 4; ni++)
#pragma unroll
                        for (int j = 0; j < 2; j++) {
                            const int n_l = wn * 32 + ni * 8 + 2 * (lane & 3) + j;
                            float val = acc[mi][ni][hh * 2 + j];
                            float uu = __ldg(ubase + (size_t)(n0c + n_l) * MPTS + mi * 16 + hh * 8);
                            float t1 = -logf(uu + EPSF);
                            float g  = -logf(t1 + EPSF);
                            uint32_t ek = enc_f(val + g);
                            if (ek > bk) { bk = ek; bn = n0c + n_l; }
                            acc[mi][ni][hh * 2 + j] = 0.0f;
                        }
                    bestk[slot] = ((unsigned long long)bk << 32) | (0xFFFFFFFFu - (uint32_t)bn);
                }
        }
    }

    // reduce
#pragma unroll
    for (int mi = 0; mi < 4; mi++)
#pragma unroll
        for (int hh = 0; hh < 2; hh++) {
            int m_local = wm * 64 + mi * 16 + hh * 8 + (lane >> 2);
            atomicMax(&sBest[m_local], bestk[mi * 2 + hh]);
        }
    __syncthreads();
    if (t < 128) atomicMax(&g_best[(size_t)b * MPTS + mt * 128 + t], sBest[t]);
}

// ---------------- kernel C: decode idx, write xyz + indices ----------------
__global__ void k_pick(const float* __restrict__ xyzs, float* __restrict__ out) {
    int i = blockIdx.x * blockDim.x + threadIdx.x;
    if (i >= NB * MPTS) return;
    int b = i / MPTS;
    unsigned long long key = g_best[i];
    int n = (int)(0xFFFFFFFFu - (unsigned int)(key & 0xFFFFFFFFull));
    g_idx[i] = n;
    const float* x = xyzs + ((size_t)b * NPTS + n) * 3;
    out[XYZ_OFF + 3 * i + 0] = x[0];
    out[XYZ_OFF + 3 * i + 1] = x[1];
    out[XYZ_OFF + 3 * i + 2] = x[2];
    out[IDX_OFF + i] = (float)n;
}

// ---------------- kernel D: gather features (b, Cout, M) ----------------
__global__ void k_gather(float* __restrict__ out) {
    int j = blockIdx.x * blockDim.x + threadIdx.x;
    if (j >= NB * COUT * MPTS) return;
    int b = j / (COUT * MPTS);
    int d = (j / MPTS) % COUT;
    int m = j % MPTS;
    int n = g_idx[b * MPTS + m];
    out[FEAT_OFF + j] = g_f[((size_t)b * NPTS + n) * COUT + d];
}

// ---------------- launch ----------------
extern "C" void kernel_launch(void* const* d_in, const int* in_sizes, int n_in,
                              void* d_out, int out_size) {
    const float* xyzs  = (const float*)d_in[0];
    const float* feats = (const float*)d_in[1];
    const float* u     = (const float*)d_in[2];
    const float* W1    = (const float*)d_in[3];
    const float* b1    = (const float*)d_in[4];
    const float* W2    = (const float*)d_in[5];
    // d_in[6] = b2: constant per m-column -> cannot change the argmax; unused.
    float* out = (float*)d_out;

    const int smemA = (64 * 132 + 64 * 128) * 4;
    cudaFuncSetAttribute(k_feat, cudaFuncAttributeMaxDynamicSharedMemorySize, smemA);
    cudaFuncSetAttribute(k_main, cudaFuncAttributeMaxDynamicSharedMemorySize, SM_TOT);

    k_init<<<(NB * MPTS + 255) / 256, 256>>>();
    k_w2split<<<MTILES, 128>>>(W2);
    k_feat<<<dim3(NTILES, NB), 256, smemA>>>(feats, W1, b1);
    k_main<<<dim3(MTILES, NSPLIT, NB), 256, SM_TOT>>>(u);
    k_pick<<<(NB * MPTS + 255) / 256, 256>>>(xyzs, out);
    k_gather<<<(NB * COUT * MPTS + 255) / 256, 256>>>(out);
}